// round 14
// baseline (speedup 1.0000x reference)
#include <cuda_runtime.h>
#include <math.h>

#define KLEN   4096
#define NFREQ  2049      // K/2 + 1
#define NH     1025      // folded freqs h=0..1024 (f=h pairs with f=2048-h)
#define NSIG   12
#define NBATCH 64
#define NLAG   51        // 2*25 + 1
#define NTAU   26        // tau = 0..25
#define NTP    13        // tau pairs (even, odd)
#define NPAIR  78        // 12*13/2 unique (n<=m) pairs
#define NS     9         // frequency slices (144 CTAs)
#define CH     114       // folded freqs per slice (9*114 = 1026 >= 1025)
#define CHH    57        // half-slice per thread (2 halves combine in-CTA)
#define CHP    115       // padded smem stride (conflict-free float4 su loads)
#define BPG    4         // batches per gcc CTA
#define GCC_BLOCK 640    // 8 groups x 80 threads = 4 batches x 2 freq-halves
#define OUTB   (NSIG*NSIG*NLAG)   // 7344 floats per batch

// -------- device scratch (static: no allocations allowed) --------
__device__ float2 g_dft2[36 * 64];                // (c,s) of 2*pi*j*a/64, rows j=0..35
__device__ float4 g_dft4[36 * 64];                // (c,c,s,s) duplicated-pair form
__device__ float4 g_tw1[33 * 64];                 // [d][b]: (c, s, tmr, tms) stage-1 twiddle
__device__ float4 g_lagp[NH * NTP];               // (wcE, wcO, wsE, wsO) at [h*13+tp]
__device__ float2 g_spec[NBATCH * NSIG * NFREQ];  // PHAT-normalized spectra
__device__ unsigned long long g_part2[NS][NBATCH][NPAIR][NTAU];  // packed (g+, g-)

// -------- packed fp32x2 helpers --------
__device__ __forceinline__ unsigned long long fma_x2(unsigned long long a,
                                                     unsigned long long b,
                                                     unsigned long long c) {
    unsigned long long d;
    asm("fma.rn.f32x2 %0, %1, %2, %3;" : "=l"(d) : "l"(a), "l"(b), "l"(c));
    return d;
}
__device__ __forceinline__ unsigned long long pack2(float lo, float hi) {
    unsigned long long d;
    asm("mov.b64 %0, {%1, %2};" : "=l"(d) : "f"(lo), "f"(hi));
    return d;
}
__device__ __forceinline__ void unpack2(unsigned long long v, float& lo, float& hi) {
    asm("mov.b64 {%0, %1}, %2;" : "=f"(lo), "=f"(hi) : "l"(v));
}

// ================= init: twiddle tables =================
__global__ void init_tables_kernel() {
    int t = blockIdx.x * blockDim.x + threadIdx.x;
    int stride = gridDim.x * blockDim.x;
    for (int i = t; i < 36 * 64; i += stride) {
        int j = i >> 6, a = i & 63;
        float s, c;
        sincospif((float)(j * a) * (1.0f / 32.0f), &s, &c);   // 2*pi*j*a/64
        g_dft2[i] = make_float2(c, s);
        g_dft4[i] = make_float4(c, c, s, s);
    }
    for (int i = t; i < 33 * 64; i += stride) {
        int d = i >> 6, b = i & 63;
        float s, c, es, ec;
        sincospif((float)(b * d) * (1.0f / 2048.0f), &s, &c);   // W4096^{bd} = c - i s
        sincospif((float)b * (1.0f / 32.0f), &es, &ec);          // 2*pi*b/64
        float tmr = ec * c + es * s;     // cos(2pi b/64 - th)
        float tms = es * c - ec * s;     // sin(2pi b/64 - th)
        g_tw1[i] = make_float4(c, s, tmr, tms);
    }
    for (int i = t; i < NH * NTP; i += stride) {
        int h = i / NTP, tp = i - h * NTP;
        int tau0 = 2 * tp, tau1 = tau0 + 1;
        float s0, c0, s1, c1;
        sincospif((float)(h * tau0) * (1.0f / 2048.0f), &s0, &c0);
        sincospif((float)(h * tau1) * (1.0f / 2048.0f), &s1, &c1);
        float w = ((h == 0) ? 1.0f : 2.0f) * (1.0f / (float)KLEN);
        g_lagp[i] = make_float4(w * c0, w * c1, w * s0, w * s1);
    }
}

// ================= FFT (64x64 four-step, fully folded, packed stage 2) + PHAT ========
// R13 packed math, but ALL twiddle-table reads are warp-uniform -> read from GLOBAL
// (L1 broadcast) instead of smem. fft smem drops 105 KB -> 50 KB => 4 CTAs/SM,
// 2 waves (the R13 regression was 2->3 wave quantization from the smem bloat).
__global__ __launch_bounds__(256) void fft_phat_kernel(const float* __restrict__ x) {
    extern __shared__ float smem[];
    float2* xf = (float2*)smem;              // [32][64]: (xe,-xo); a=0 -> (x0,x32)
    float2* Yt = xf + 32 * 64;               // [b][d]: b*66 + d

    const int t = threadIdx.x;
    const float* xin = x + (size_t)blockIdx.x * KLEN;

    for (int i = t; i < 32 * 64; i += 256) {
        int a = i >> 6, b = i & 63;
        if (a == 0) {
            xf[b] = make_float2(xin[b], xin[32 * 64 + b]);
        } else {
            float v1 = xin[a * 64 + b];
            float v2 = xin[(64 - a) * 64 + b];
            xf[a * 64 + b] = make_float2(v1 + v2, v2 - v1);   // (xe, -xo)
        }
    }
    __syncthreads();

    const int bb = t & 63, q0 = t >> 6;

    // ---- stage 1: 9 packed accumulators (yr, yi) for d = q0 + 4i ----
    {
        unsigned long long acc[9];
        #pragma unroll
        for (int i = 0; i < 9; i++) acc[i] = 0ull;

        {
            unsigned long long vp = *(const unsigned long long*)(xf + 64 + bb);
            #pragma unroll
            for (int i = 0; i < 9; i++) {
                int d = q0 + 4 * i;
                unsigned long long cs = *(const unsigned long long*)(g_dft2 + d * 64 + 1);
                acc[i] = fma_x2(vp, cs, acc[i]);
            }
        }
        for (int a = 2; a < 32; a += 2) {
            unsigned long long vp0 = *(const unsigned long long*)(xf + a * 64 + bb);
            unsigned long long vp1 = *(const unsigned long long*)(xf + (a + 1) * 64 + bb);
            #pragma unroll
            for (int i = 0; i < 9; i++) {
                int d = q0 + 4 * i;                    // d<=35; padded rows, junk discarded
                longlong2 w = *(const longlong2*)(g_dft2 + d * 64 + a);   // uniform LDG
                acc[i] = fma_x2(vp0, (unsigned long long)w.x, acc[i]);
                acc[i] = fma_x2(vp1, (unsigned long long)w.y, acc[i]);
            }
        }

        float2 x03 = xf[bb];           // (x0, x32)
        #pragma unroll
        for (int i = 0; i < 9; i++) {
            int d = q0 + 4 * i;
            if (d <= 32) {
                float yr, yi;
                unpack2(acc[i], yr, yi);
                yr += x03.x + ((d & 1) ? -x03.y : x03.y);
                float4 w = g_tw1[d * 64 + bb];          // (c, s, tmr, tms)
                Yt[bb * 66 + d] = make_float2(yr * w.x + yi * w.y, yi * w.x - yr * w.y);
                if (d >= 1 && d <= 31) {
                    Yt[bb * 66 + (64 - d)] =
                        make_float2(yr * w.z - yi * w.w, -(yr * w.w + yi * w.z));
                }
            }
        }
    }
    __syncthreads();

    // ---- stage 2: d = bb, cc = q0 + 4j; b-folded, fully packed, global twiddles ----
    {
        const int d = bb;
        unsigned long long accC[9], accS[9];
        float2 z0  = Yt[d];
        float2 z32 = Yt[32 * 66 + d];
        #pragma unroll
        for (int j = 0; j < 9; j++) {
            int cc = q0 + 4 * j;
            float sg = (cc & 1) ? -1.f : 1.f;
            accC[j] = pack2(z0.x + sg * z32.x, z0.y + sg * z32.y);
            accS[j] = 0ull;
        }

        // b = 1 (scalar head)
        {
            float2 z1 = Yt[66 + d];
            float2 z2 = Yt[63 * 66 + d];
            unsigned long long pe = pack2(z1.x + z2.x, z1.y + z2.y);
            unsigned long long po = pack2(z1.x - z2.x, z1.y - z2.y);
            #pragma unroll
            for (int j = 0; j < 9; j++) {
                int cc = q0 + 4 * j;
                longlong2 w = *(const longlong2*)(g_dft4 + cc * 64 + 1); // uniform LDG
                accC[j] = fma_x2(pe, (unsigned long long)w.x, accC[j]);
                accS[j] = fma_x2(po, (unsigned long long)w.y, accS[j]);
            }
        }
        // b = 2..31 in pairs
        for (int b = 2; b < 32; b += 2) {
            float2 z1a = Yt[b * 66 + d];
            float2 z2a = Yt[(64 - b) * 66 + d];
            float2 z1b = Yt[(b + 1) * 66 + d];
            float2 z2b = Yt[(63 - b) * 66 + d];
            unsigned long long pe0 = pack2(z1a.x + z2a.x, z1a.y + z2a.y);
            unsigned long long po0 = pack2(z1a.x - z2a.x, z1a.y - z2a.y);
            unsigned long long pe1 = pack2(z1b.x + z2b.x, z1b.y + z2b.y);
            unsigned long long po1 = pack2(z1b.x - z2b.x, z1b.y - z2b.y);
            #pragma unroll
            for (int j = 0; j < 9; j++) {
                int cc = q0 + 4 * j;                   // <=35; padded rows, junk discarded
                longlong2 w0 = *(const longlong2*)(g_dft4 + cc * 64 + b);
                longlong2 w1 = *(const longlong2*)(g_dft4 + cc * 64 + b + 1);
                accC[j] = fma_x2(pe0, (unsigned long long)w0.x, accC[j]);
                accS[j] = fma_x2(po0, (unsigned long long)w0.y, accS[j]);
                accC[j] = fma_x2(pe1, (unsigned long long)w1.x, accC[j]);
                accS[j] = fma_x2(po1, (unsigned long long)w1.y, accS[j]);
            }
        }

        float2* outp = g_spec + (size_t)blockIdx.x * NFREQ;
        #pragma unroll
        for (int j = 0; j < 9; j++) {
            int cc = q0 + 4 * j;
            int f = cc * 64 + d;
            if (cc <= 32 && f <= 2048) {
                float cXr, cXi, sLo, sHi;
                unpack2(accC[j], cXr, cXi);
                unpack2(accS[j], sLo, sHi);
                float Xr = cXr + sHi;    // + sum(zoy*s)
                float Xi = cXi - sLo;    // - sum(zox*s)
                float u = fmaf(Xr, Xr, fmaf(Xi, Xi, 1e-30f));
                float inv = rsqrtf(u);
                outp[f] = make_float2(Xr * inv, Xi * inv);
            }
        }
    }
}

// ================= GCC: folded cross-spectrum x lag twiddles (frozen R12 form) =======
__global__ __launch_bounds__(GCC_BLOCK, 1) void gcc_kernel() {
    extern __shared__ float smem[];
    float4* su = (float4*)smem;                  // [BPG][12][CHP] (Ar,Ai,Br,Bi)
    float4* T  = su + BPG * NSIG * CHP;          // [CH][13] (wcE,wcO,wsE,wsO)
    unsigned long long* stage = (unsigned long long*)su;  // reused after mainloop

    const int t = threadIdx.x;
    const int bg = blockIdx.x;
    const int f0 = blockIdx.y * CH;

    for (int i = t; i < BPG * NSIG * CH; i += GCC_BLOCK) {
        int g = i / (NSIG * CH);
        int r = i - g * (NSIG * CH);
        int sig = r / CH, hl = r - sig * CH;
        int f = f0 + hl;
        const float2* sp = g_spec + ((size_t)(bg * BPG + g) * NSIG + sig) * NFREQ;
        float2 A = (f <= 1024) ? sp[f] : make_float2(0.f, 0.f);
        float2 B = (f <= 1023) ? sp[2048 - f] : make_float2(0.f, 0.f);
        su[(g * NSIG + sig) * CHP + hl] = make_float4(A.x, A.y, B.x, B.y);
    }
    for (int i = t; i < CH * NTP; i += GCC_BLOCK) {
        int hl = i / NTP;
        int f = f0 + hl;
        T[i] = (f <= 1024) ? g_lagp[f * NTP + (i - hl * NTP)]
                           : make_float4(0.f, 0.f, 0.f, 0.f);
    }
    __syncthreads();

    const int grp = t / 80, u = t - grp * 80;
    const int gb = grp >> 1;          // batch within CTA (0..3)
    const int half = grp & 1;         // frequency half
    const bool active = (u < NPAIR);

    unsigned long long accU[NTP], accV[NTP];   // lanes = (even tau, odd tau)
    #pragma unroll
    for (int i = 0; i < NTP; i++) { accU[i] = 0ull; accV[i] = 0ull; }

    if (active) {
        int n = 0, rem = u;
        #pragma unroll
        for (int k = 0; k < NSIG; k++) {
            int cnt = NSIG - k;
            if (rem < cnt) { n = k; break; }
            rem -= cnt;
        }
        const int m = n + rem;

        const float4* pn = su + gb * (NSIG * CHP) + n * CHP;
        const float4* pm = su + gb * (NSIG * CHP) + m * CHP;

        const int h0 = half * CHH;
        for (int hl = h0; hl < h0 + CHH; hl++) {
            float4 an = pn[hl];
            float4 am = pm[hl];
            float U1 = an.x * am.x + an.y * am.y;
            float V1 = an.y * am.x - an.x * am.y;
            float U2 = an.z * am.z + an.w * am.w;
            float V2 = an.w * am.z - an.z * am.w;
            unsigned long long pU = pack2(U1 + U2, U1 - U2);   // (Ue, Uo)
            unsigned long long pV = pack2(V1 - V2, V1 + V2);   // (Vme, Vpo)
            const longlong2* tw = (const longlong2*)(T + (size_t)hl * NTP);
            #pragma unroll
            for (int tp = 0; tp < NTP; tp++) {
                longlong2 w = tw[tp];   // .x = (wcE,wcO), .y = (wsE,wsO)
                accU[tp] = fma_x2((unsigned long long)w.x, pU, accU[tp]);
                accV[tp] = fma_x2((unsigned long long)w.y, pV, accV[tp]);
            }
        }
    }
    __syncthreads();   // su reads complete; staging region now safe to overwrite

    if (active && half == 1) {
        unsigned long long* st = stage + ((size_t)gb * NPAIR + u) * 26;
        #pragma unroll
        for (int tp = 0; tp < NTP; tp++) { st[tp] = accU[tp]; st[NTP + tp] = accV[tp]; }
    }
    __syncthreads();

    if (active && half == 0) {
        const unsigned long long* st = stage + ((size_t)gb * NPAIR + u) * 26;
        const unsigned long long ONE2 = pack2(1.0f, 1.0f);
        #pragma unroll
        for (int tp = 0; tp < NTP; tp++) {
            accU[tp] = fma_x2(ONE2, st[tp], accU[tp]);
            accV[tp] = fma_x2(ONE2, st[NTP + tp], accV[tp]);
        }
        unsigned long long* pr = &g_part2[blockIdx.y][bg * BPG + gb][u][0];
        #pragma unroll
        for (int tp = 0; tp < NTP; tp++) {
            float aE, aO, bE, bO;
            unpack2(accU[tp], aE, aO);
            unpack2(accV[tp], bE, bO);
            pr[2 * tp]     = pack2(aE - bE, aE + bE);   // (g+, g-) even tau
            pr[2 * tp + 1] = pack2(aO - bO, aO + bO);   // (g+, g-) odd tau
        }
    }
}

// ================= reduce partials + triangular mirror expansion (frozen R8) =========
__global__ void reduce_kernel(float* __restrict__ out) {
    int i = blockIdx.x * blockDim.x + threadIdx.x;
    if (i >= NBATCH * NPAIR * 13) return;
    int b = i / (NPAIR * 13);
    int r = i - b * (NPAIR * 13);
    int p = r / 13, k2 = r - p * 13;
    int tau0 = 2 * k2, tau1 = tau0 + 1;

    float gp0 = 0.f, gm0 = 0.f, gp1 = 0.f, gm1 = 0.f;
    #pragma unroll
    for (int s = 0; s < NS; s++) {
        ulonglong2 v = *(const ulonglong2*)&g_part2[s][b][p][tau0];
        float lo, hi;
        unpack2(v.x, lo, hi); gp0 += lo; gm0 += hi;
        unpack2(v.y, lo, hi); gp1 += lo; gm1 += hi;
    }

    int n = 0, rem = p;
    #pragma unroll
    for (int k = 0; k < NSIG; k++) {
        int cnt = NSIG - k;
        if (rem < cnt) { n = k; break; }
        rem -= cnt;
    }
    int m = n + rem;

    float* ob  = out + (size_t)b * OUTB;
    float* onm = ob + (n * NSIG + m) * NLAG;
    onm[tau0] = gp0;
    onm[tau1] = gp1;
    if (tau0 > 0) onm[NLAG - tau0] = gm0;
    onm[NLAG - tau1] = gm1;
    if (n != m) {
        float* omn = ob + (m * NSIG + n) * NLAG;
        omn[tau0] = gm0;
        omn[tau1] = gm1;
        if (tau0 > 0) omn[NLAG - tau0] = gp0;
        omn[NLAG - tau1] = gp1;
    }
}

// ================= launch =================
extern "C" void kernel_launch(void* const* d_in, const int* in_sizes, int n_in,
                              void* d_out, int out_size) {
    const float* x = (const float*)d_in[0];
    float* out = (float*)d_out;

    const int fft_smem = 32 * 64 * (int)sizeof(float2)      // xf  16,384
                       + 64 * 66 * (int)sizeof(float2);     // Yt  33,792 => 50,176 B
    const int gcc_smem = BPG * NSIG * CHP * (int)sizeof(float4)
                       + CH * NTP * (int)sizeof(float4);    // 112,032 B

    cudaFuncSetAttribute(fft_phat_kernel, cudaFuncAttributeMaxDynamicSharedMemorySize, fft_smem);
    cudaFuncSetAttribute(gcc_kernel,      cudaFuncAttributeMaxDynamicSharedMemorySize, gcc_smem);

    init_tables_kernel<<<128, 256>>>();
    fft_phat_kernel<<<NBATCH * NSIG, 256, fft_smem>>>(x);
    gcc_kernel<<<dim3(NBATCH / BPG, NS), GCC_BLOCK, gcc_smem>>>();
    const int rthreads = NBATCH * NPAIR * 13;
    reduce_kernel<<<(rthreads + 255) / 256, 256>>>(out);
}

// round 15
// speedup vs baseline: 1.2547x; 1.2547x over previous
#include <cuda_runtime.h>
#include <math.h>

#define KLEN   4096
#define NFREQ  2049      // K/2 + 1
#define NH     1025      // folded freqs h=0..1024 (f=h pairs with f=2048-h)
#define NSIG   12
#define NBATCH 64
#define NLAG   51        // 2*25 + 1
#define NTAU   26        // tau = 0..25
#define NTP    13        // tau pairs (even, odd)
#define NPAIR  78        // 12*13/2 unique (n<=m) pairs
#define NS     9         // frequency slices (144 CTAs, all co-resident)
#define NCTA   (16 * NS) // 144 gcc CTAs
#define CH     114       // folded freqs per slice (9*114 = 1026 >= 1025)
#define CHH    57        // half-slice per thread (2 halves combine in-CTA)
#define CHP    115       // padded smem stride (conflict-free float4 su loads)
#define BPG    4         // batches per gcc CTA
#define GCC_BLOCK 640    // 8 groups x 80 threads = 4 batches x 2 freq-halves
#define OUTB   (NSIG*NSIG*NLAG)   // 7344 floats per batch

// -------- device scratch (static: no allocations allowed) --------
__device__ float2 g_dft2[36 * 64];                // (c,s) of 2*pi*j*a/64, rows j=0..35
__device__ float4 g_tw1[33 * 64];                 // [d][b]: (c, s, tmr, tms) stage-1 twiddle
__device__ float4 g_lagp[NH * NTP];               // (wcE, wcO, wsE, wsO) at [h*13+tp]
__device__ float2 g_spec[NBATCH * NSIG * NFREQ];  // PHAT-normalized spectra
__device__ unsigned long long g_part2[NS][NBATCH][NPAIR][NTAU];  // packed (g+, g-)
__device__ unsigned int g_bar;                    // gcc grid barrier (reset by init)

// -------- packed fp32x2 helpers --------
__device__ __forceinline__ unsigned long long fma_x2(unsigned long long a,
                                                     unsigned long long b,
                                                     unsigned long long c) {
    unsigned long long d;
    asm("fma.rn.f32x2 %0, %1, %2, %3;" : "=l"(d) : "l"(a), "l"(b), "l"(c));
    return d;
}
__device__ __forceinline__ unsigned long long pack2(float lo, float hi) {
    unsigned long long d;
    asm("mov.b64 %0, {%1, %2};" : "=l"(d) : "f"(lo), "f"(hi));
    return d;
}
__device__ __forceinline__ void unpack2(unsigned long long v, float& lo, float& hi) {
    asm("mov.b64 {%0, %1}, %2;" : "=f"(lo), "=f"(hi) : "l"(v));
}

// ================= init: twiddle tables + barrier reset =================
__global__ void init_tables_kernel() {
    int t = blockIdx.x * blockDim.x + threadIdx.x;
    int stride = gridDim.x * blockDim.x;
    if (blockIdx.x == 0 && threadIdx.x == 0) g_bar = 0u;
    for (int i = t; i < 36 * 64; i += stride) {
        int j = i >> 6, a = i & 63;
        float s, c;
        sincospif((float)(j * a) * (1.0f / 32.0f), &s, &c);   // 2*pi*j*a/64
        g_dft2[i] = make_float2(c, s);
    }
    for (int i = t; i < 33 * 64; i += stride) {
        int d = i >> 6, b = i & 63;
        float s, c, es, ec;
        sincospif((float)(b * d) * (1.0f / 2048.0f), &s, &c);   // W4096^{bd} = c - i s
        sincospif((float)b * (1.0f / 32.0f), &es, &ec);          // 2*pi*b/64
        float tmr = ec * c + es * s;     // cos(2pi b/64 - th)
        float tms = es * c - ec * s;     // sin(2pi b/64 - th)
        g_tw1[i] = make_float4(c, s, tmr, tms);
    }
    for (int i = t; i < NH * NTP; i += stride) {
        int h = i / NTP, tp = i - h * NTP;
        int tau0 = 2 * tp, tau1 = tau0 + 1;
        float s0, c0, s1, c1;
        sincospif((float)(h * tau0) * (1.0f / 2048.0f), &s0, &c0);
        sincospif((float)(h * tau1) * (1.0f / 2048.0f), &s1, &c1);
        float w = ((h == 0) ? 1.0f : 2.0f) * (1.0f / (float)KLEN);
        g_lagp[i] = make_float4(w * c0, w * c1, w * s0, w * s1);
    }
}

// ================= FFT (64x64 four-step, fully folded) + PHAT ========================
// Exact R12 form (measured best): smem twiddle tables, packed stage 1, scalar stage 2,
// SoA Y stride 65, g_tw1 epilogue, rsqrt PHAT. 68.1 KB smem -> 3 CTAs/SM, 2 waves.
__global__ __launch_bounds__(256) void fft_phat_kernel(const float* __restrict__ x) {
    extern __shared__ float smem[];
    float2* xf  = (float2*)smem;            // [32][64]: (xe,-xo); a=0 -> (x0,x32)
    float*  Yr  = (float*)(xf + 32 * 64);   // [64 b][65] (col d), odd stride
    float*  Yi  = Yr + 64 * 65;
    float2* dft = (float2*)(Yi + 64 * 65);  // rows j=0..32 valid; padded to 36 rows

    const int t = threadIdx.x;
    const float* xin = x + (size_t)blockIdx.x * KLEN;

    for (int i = t; i < 36 * 64; i += 256) dft[i] = g_dft2[i];
    for (int i = t; i < 32 * 64; i += 256) {
        int a = i >> 6, b = i & 63;
        if (a == 0) {
            xf[b] = make_float2(xin[b], xin[32 * 64 + b]);
        } else {
            float v1 = xin[a * 64 + b];
            float v2 = xin[(64 - a) * 64 + b];
            xf[a * 64 + b] = make_float2(v1 + v2, v2 - v1);   // (xe, -xo)
        }
    }
    __syncthreads();

    const int bb = t & 63, q0 = t >> 6;

    // ---- stage 1: 9 packed accumulators (yr, yi) for d = q0 + 4i ----
    {
        unsigned long long acc[9];
        #pragma unroll
        for (int i = 0; i < 9; i++) acc[i] = 0ull;

        {
            unsigned long long vp = *(const unsigned long long*)(xf + 64 + bb);
            #pragma unroll
            for (int i = 0; i < 9; i++) {
                int d = q0 + 4 * i;
                unsigned long long cs = *(const unsigned long long*)(dft + d * 64 + 1);
                acc[i] = fma_x2(vp, cs, acc[i]);
            }
        }
        for (int a = 2; a < 32; a += 2) {
            unsigned long long vp0 = *(const unsigned long long*)(xf + a * 64 + bb);
            unsigned long long vp1 = *(const unsigned long long*)(xf + (a + 1) * 64 + bb);
            #pragma unroll
            for (int i = 0; i < 9; i++) {
                int d = q0 + 4 * i;                    // d<=35; padded rows, junk discarded
                longlong2 w = *(const longlong2*)(dft + d * 64 + a);
                acc[i] = fma_x2(vp0, (unsigned long long)w.x, acc[i]);
                acc[i] = fma_x2(vp1, (unsigned long long)w.y, acc[i]);
            }
        }

        float2 x03 = xf[bb];           // (x0, x32)
        #pragma unroll
        for (int i = 0; i < 9; i++) {
            int d = q0 + 4 * i;
            if (d <= 32) {
                float yr, yi;
                unpack2(acc[i], yr, yi);
                yr += x03.x + ((d & 1) ? -x03.y : x03.y);
                float4 w = g_tw1[d * 64 + bb];          // (c, s, tmr, tms)
                Yr[bb * 65 + d] = yr * w.x + yi * w.y;
                Yi[bb * 65 + d] = yi * w.x - yr * w.y;
                if (d >= 1 && d <= 31) {
                    Yr[bb * 65 + (64 - d)] = yr * w.z - yi * w.w;
                    Yi[bb * 65 + (64 - d)] = -(yr * w.w + yi * w.z);
                }
            }
        }
    }
    __syncthreads();

    // ---- stage 2: d = bb, cc = q0 + 4j; b-folded, x2-unrolled with 16B twiddles ----
    {
        const int d = bb;
        float Xr[9], Xi[9];
        float z0r = Yr[d],           z0i = Yi[d];
        float z32r = Yr[32 * 65 + d], z32i = Yi[32 * 65 + d];
        #pragma unroll
        for (int j = 0; j < 9; j++) {
            int cc = q0 + 4 * j;
            float sg = (cc & 1) ? -1.f : 1.f;
            Xr[j] = z0r + sg * z32r;
            Xi[j] = z0i + sg * z32i;
        }

        {
            float z1r = Yr[65 + d],        z1i = Yi[65 + d];
            float z2r = Yr[63 * 65 + d],   z2i = Yi[63 * 65 + d];
            float zex = z1r + z2r, zey = z1i + z2i;
            float zox = z1r - z2r, zoy = z1i - z2i;
            #pragma unroll
            for (int j = 0; j < 9; j++) {
                int cc = q0 + 4 * j;
                float2 cs = dft[cc * 64 + 1];
                Xr[j] += zex * cs.x + zoy * cs.y;
                Xi[j] += zey * cs.x - zox * cs.y;
            }
        }
        for (int b = 2; b < 32; b += 2) {
            float z1r0 = Yr[b * 65 + d],          z1i0 = Yi[b * 65 + d];
            float z2r0 = Yr[(64 - b) * 65 + d],   z2i0 = Yi[(64 - b) * 65 + d];
            float z1r1 = Yr[(b + 1) * 65 + d],    z1i1 = Yi[(b + 1) * 65 + d];
            float z2r1 = Yr[(63 - b) * 65 + d],   z2i1 = Yi[(63 - b) * 65 + d];
            float zex0 = z1r0 + z2r0, zey0 = z1i0 + z2i0;
            float zox0 = z1r0 - z2r0, zoy0 = z1i0 - z2i0;
            float zex1 = z1r1 + z2r1, zey1 = z1i1 + z2i1;
            float zox1 = z1r1 - z2r1, zoy1 = z1i1 - z2i1;
            #pragma unroll
            for (int j = 0; j < 9; j++) {
                int cc = q0 + 4 * j;                   // <=35; padded rows, junk discarded
                float4 cs = *(const float4*)(dft + cc * 64 + b);
                Xr[j] += zex0 * cs.x + zoy0 * cs.y;
                Xi[j] += zey0 * cs.x - zox0 * cs.y;
                Xr[j] += zex1 * cs.z + zoy1 * cs.w;
                Xi[j] += zey1 * cs.z - zox1 * cs.w;
            }
        }

        float2* outp = g_spec + (size_t)blockIdx.x * NFREQ;
        #pragma unroll
        for (int j = 0; j < 9; j++) {
            int cc = q0 + 4 * j;
            int f = cc * 64 + d;
            if (cc <= 32 && f <= 2048) {
                float u = fmaf(Xr[j], Xr[j], fmaf(Xi[j], Xi[j], 1e-30f));
                float inv = rsqrtf(u);
                outp[f] = make_float2(Xr[j] * inv, Xi[j] * inv);
            }
        }
    }
}

// ================= GCC + fused reduce ================================================
// R12 gcc body, then: software grid barrier (144 CTAs all co-resident at 640thr/112KB),
// then each CTA reduces 1/144 of (batch, pair, tau-pair) items — reduce kernel deleted.
__global__ __launch_bounds__(GCC_BLOCK, 1) void gcc_kernel(float* __restrict__ out) {
    extern __shared__ float smem[];
    float4* su = (float4*)smem;                  // [BPG][12][CHP] (Ar,Ai,Br,Bi)
    float4* T  = su + BPG * NSIG * CHP;          // [CH][13] (wcE,wcO,wsE,wsO)
    unsigned long long* stage = (unsigned long long*)su;  // reused after mainloop

    const int t = threadIdx.x;
    const int bg = blockIdx.x;
    const int f0 = blockIdx.y * CH;

    for (int i = t; i < BPG * NSIG * CH; i += GCC_BLOCK) {
        int g = i / (NSIG * CH);
        int r = i - g * (NSIG * CH);
        int sig = r / CH, hl = r - sig * CH;
        int f = f0 + hl;
        const float2* sp = g_spec + ((size_t)(bg * BPG + g) * NSIG + sig) * NFREQ;
        float2 A = (f <= 1024) ? sp[f] : make_float2(0.f, 0.f);
        float2 B = (f <= 1023) ? sp[2048 - f] : make_float2(0.f, 0.f);
        su[(g * NSIG + sig) * CHP + hl] = make_float4(A.x, A.y, B.x, B.y);
    }
    for (int i = t; i < CH * NTP; i += GCC_BLOCK) {
        int hl = i / NTP;
        int f = f0 + hl;
        T[i] = (f <= 1024) ? g_lagp[f * NTP + (i - hl * NTP)]
                           : make_float4(0.f, 0.f, 0.f, 0.f);
    }
    __syncthreads();

    const int grp = t / 80, u = t - grp * 80;
    const int gb = grp >> 1;          // batch within CTA (0..3)
    const int half = grp & 1;         // frequency half
    const bool active = (u < NPAIR);

    unsigned long long accU[NTP], accV[NTP];   // lanes = (even tau, odd tau)
    #pragma unroll
    for (int i = 0; i < NTP; i++) { accU[i] = 0ull; accV[i] = 0ull; }

    if (active) {
        int n = 0, rem = u;
        #pragma unroll
        for (int k = 0; k < NSIG; k++) {
            int cnt = NSIG - k;
            if (rem < cnt) { n = k; break; }
            rem -= cnt;
        }
        const int m = n + rem;

        const float4* pn = su + gb * (NSIG * CHP) + n * CHP;
        const float4* pm = su + gb * (NSIG * CHP) + m * CHP;

        const int h0 = half * CHH;
        for (int hl = h0; hl < h0 + CHH; hl++) {
            float4 an = pn[hl];
            float4 am = pm[hl];
            float U1 = an.x * am.x + an.y * am.y;
            float V1 = an.y * am.x - an.x * am.y;
            float U2 = an.z * am.z + an.w * am.w;
            float V2 = an.w * am.z - an.z * am.w;
            unsigned long long pU = pack2(U1 + U2, U1 - U2);   // (Ue, Uo)
            unsigned long long pV = pack2(V1 - V2, V1 + V2);   // (Vme, Vpo)
            const longlong2* tw = (const longlong2*)(T + (size_t)hl * NTP);
            #pragma unroll
            for (int tp = 0; tp < NTP; tp++) {
                longlong2 w = tw[tp];   // .x = (wcE,wcO), .y = (wsE,wsO)
                accU[tp] = fma_x2((unsigned long long)w.x, pU, accU[tp]);
                accV[tp] = fma_x2((unsigned long long)w.y, pV, accV[tp]);
            }
        }
    }
    __syncthreads();   // su reads complete; staging region now safe to overwrite

    if (active && half == 1) {
        unsigned long long* st = stage + ((size_t)gb * NPAIR + u) * 26;
        #pragma unroll
        for (int tp = 0; tp < NTP; tp++) { st[tp] = accU[tp]; st[NTP + tp] = accV[tp]; }
    }
    __syncthreads();

    if (active && half == 0) {
        const unsigned long long* st = stage + ((size_t)gb * NPAIR + u) * 26;
        const unsigned long long ONE2 = pack2(1.0f, 1.0f);
        #pragma unroll
        for (int tp = 0; tp < NTP; tp++) {
            accU[tp] = fma_x2(ONE2, st[tp], accU[tp]);
            accV[tp] = fma_x2(ONE2, st[NTP + tp], accV[tp]);
        }
        unsigned long long* pr = &g_part2[blockIdx.y][bg * BPG + gb][u][0];
        #pragma unroll
        for (int tp = 0; tp < NTP; tp++) {
            float aE, aO, bE, bO;
            unpack2(accU[tp], aE, aO);
            unpack2(accV[tp], bE, bO);
            pr[2 * tp]     = pack2(aE - bE, aE + bE);   // (g+, g-) even tau
            pr[2 * tp + 1] = pack2(aO - bO, aO + bO);   // (g+, g-) odd tau
        }
    }

    // ---- software grid barrier: all 144 CTAs co-resident (640 thr, 112 KB smem) ----
    __syncthreads();
    __threadfence();                      // release partials
    if (t == 0) {
        atomicAdd(&g_bar, 1u);
        while (atomicAdd(&g_bar, 0u) < (unsigned)NCTA) { }
    }
    __syncthreads();
    __threadfence();                      // acquire all CTAs' partials

    // ---- fused reduce: one (batch, pair, tau-pair) item per thread ----
    {
        const int cta = blockIdx.y * gridDim.x + blockIdx.x;
        int i = cta * GCC_BLOCK + t;
        if (i < NBATCH * NPAIR * 13) {
            int b = i / (NPAIR * 13);
            int r = i - b * (NPAIR * 13);
            int p = r / 13, k2 = r - p * 13;
            int tau0 = 2 * k2, tau1 = tau0 + 1;

            float gp0 = 0.f, gm0 = 0.f, gp1 = 0.f, gm1 = 0.f;
            #pragma unroll
            for (int s = 0; s < NS; s++) {
                ulonglong2 v = *(const ulonglong2*)&g_part2[s][b][p][tau0];
                float lo, hi;
                unpack2(v.x, lo, hi); gp0 += lo; gm0 += hi;
                unpack2(v.y, lo, hi); gp1 += lo; gm1 += hi;
            }

            int n = 0, rem = p;
            #pragma unroll
            for (int k = 0; k < NSIG; k++) {
                int cnt = NSIG - k;
                if (rem < cnt) { n = k; break; }
                rem -= cnt;
            }
            int m = n + rem;

            float* ob  = out + (size_t)b * OUTB;
            float* onm = ob + (n * NSIG + m) * NLAG;
            onm[tau0] = gp0;
            onm[tau1] = gp1;
            if (tau0 > 0) onm[NLAG - tau0] = gm0;
            onm[NLAG - tau1] = gm1;
            if (n != m) {
                float* omn = ob + (m * NSIG + n) * NLAG;
                omn[tau0] = gm0;
                omn[tau1] = gm1;
                if (tau0 > 0) omn[NLAG - tau0] = gp0;
                omn[NLAG - tau1] = gp1;
            }
        }
    }
}

// ================= launch =================
extern "C" void kernel_launch(void* const* d_in, const int* in_sizes, int n_in,
                              void* d_out, int out_size) {
    const float* x = (const float*)d_in[0];
    float* out = (float*)d_out;

    const int fft_smem = 32 * 64 * (int)sizeof(float2)      // xf      16,384
                       + 2 * 64 * 65 * (int)sizeof(float)   // Yr, Yi  33,280
                       + 36 * 64 * (int)sizeof(float2);     // dft     18,432 => 68,096
    const int gcc_smem = BPG * NSIG * CHP * (int)sizeof(float4)
                       + CH * NTP * (int)sizeof(float4);    // 112,032 B

    cudaFuncSetAttribute(fft_phat_kernel, cudaFuncAttributeMaxDynamicSharedMemorySize, fft_smem);
    cudaFuncSetAttribute(gcc_kernel,      cudaFuncAttributeMaxDynamicSharedMemorySize, gcc_smem);

    init_tables_kernel<<<128, 256>>>();
    fft_phat_kernel<<<NBATCH * NSIG, 256, fft_smem>>>(x);
    gcc_kernel<<<dim3(NBATCH / BPG, NS), GCC_BLOCK, gcc_smem>>>(out);
}